// round 14
// baseline (speedup 1.0000x reference)
#include <cuda_runtime.h>
#include <cuda_bf16.h>
#include <stdint.h>
#include <math.h>

#define NTOK  16384
#define BATCH 8
#define SEQ   2048
#define DM    256
#define DI    512
#define DS    16

// weight scratch layout per layer: [inw 1024*256 | xpw 48*512 | ow 256*512]
#define W_INP_SZ (1024 * 256)
#define W_XP_OFF W_INP_SZ
#define W_XP_SZ  (48 * 512)
#define W_OW_OFF (W_XP_OFF + W_XP_SZ)
#define W_OW_SZ  (256 * 512)
#define W_LAYER  (W_OW_OFF + W_OW_SZ)

// ---------------- scratch (allocation-free: __device__ globals) ----------------
__device__ __nv_bfloat16 g_lnbf[NTOK * DM];     // layernorm output (bf16)
__device__ __nv_bfloat16 g_xzbf[NTOK * 2 * DI]; // in_proj output (u | z) bf16
__device__ __nv_bfloat16 g_ubf[NTOK * DI];      // conv+silu output (bf16)
__device__ float         g_xdbl[NTOK * 48];     // x_proj output (dt_r | B | C)
__device__ __nv_bfloat16 g_ybf[NTOK * DI];      // scan output, gated (bf16)
__device__ __nv_bfloat16 g_wbf[2 * W_LAYER];    // bf16 weights

__device__ __forceinline__ float sigmoidf_(float v) { return 1.f / (1.f + __expf(-v)); }

__device__ __forceinline__ unsigned smem_u32(const void* p) {
    return (unsigned)__cvta_generic_to_shared(p);
}
__device__ __forceinline__ void cp16(unsigned dst, const void* src) {
    asm volatile("cp.async.cg.shared.global [%0], [%1], 16;" :: "r"(dst), "l"(src));
}

// ---------------- one-shot weight conversion fp32 -> bf16 -----------------------
__global__ void convert_weights(const float* __restrict__ inw,
                                const float* __restrict__ xpw,
                                const float* __restrict__ ow) {
    int idx = blockIdx.x * 256 + threadIdx.x;
    if (idx >= 2 * W_LAYER) return;
    int layer = idx / W_LAYER, r = idx % W_LAYER;
    float v;
    if (r < W_INP_SZ)       v = inw[(size_t)layer * W_INP_SZ + r];
    else if (r < W_OW_OFF)  v = xpw[(size_t)layer * W_XP_SZ + (r - W_XP_OFF)];
    else                    v = ow[(size_t)layer * W_OW_SZ + (r - W_OW_OFF)];
    g_wbf[idx] = __float2bfloat16(v);
}

// ---------------- layernorm: one warp per token, writes bf16 --------------------
__global__ void ln_kernel(const float* __restrict__ x,
                          const float* __restrict__ g,
                          const float* __restrict__ b) {
    int warp = threadIdx.x >> 5, lane = threadIdx.x & 31;
    int tok = blockIdx.x * 8 + warp;
    const float* row = x + (size_t)tok * DM;
    float v[8];
    float s = 0.f, s2 = 0.f;
#pragma unroll
    for (int i = 0; i < 8; i++) {
        v[i] = row[lane + i * 32];
        s += v[i];
        s2 += v[i] * v[i];
    }
#pragma unroll
    for (int o = 16; o; o >>= 1) {
        s  += __shfl_xor_sync(0xffffffffu, s, o);
        s2 += __shfl_xor_sync(0xffffffffu, s2, o);
    }
    float m   = s * (1.f / DM);
    float var = s2 * (1.f / DM) - m * m;
    float inv = rsqrtf(var + 1e-5f);
    __nv_bfloat16* o = g_lnbf + (size_t)tok * DM;
#pragma unroll
    for (int i = 0; i < 8; i++) {
        int c = lane + i * 32;
        o[c] = __float2bfloat16((v[i] - m) * inv * g[c] + b[c]);
    }
}

// ============ BIG bf16 GEMM: 128x128x32, m16n8k16, 3-stage cp.async =============
// EPI 0: C is bf16 (plain store). EPI 1: C is fp32, res + ls[n]*acc.
#define BB_STR  40
#define BB_ABUF (128 * BB_STR)
#define BB_STAGE (2 * BB_ABUF)
#define GEMMB_SMEM (3 * BB_STAGE * 2)

template <int EPI>
__global__ __launch_bounds__(256)
void gemm_bf_big(const __nv_bfloat16* __restrict__ A, int lda,
                 const __nv_bfloat16* __restrict__ W,
                 void* __restrict__ Cptr,
                 int N, int K,
                 const float* __restrict__ res,
                 const float* __restrict__ ls) {
    extern __shared__ char smem_raw[];
    __nv_bfloat16* dyn = (__nv_bfloat16*)smem_raw;

    const int tid = threadIdx.x;
    const int warp = tid >> 5, lane = tid & 31;
    const int wm = (warp >> 2) * 64;
    const int wn = (warp & 3) * 32;
    const int m0 = blockIdx.y * 128, n0 = blockIdx.x * 128;
    const int lq = lane >> 2, lp = lane & 3;

    auto issue_tile = [&](int st, int k0) {
        __nv_bfloat16* As = dyn + st * BB_STAGE;
        __nv_bfloat16* Ws = As + BB_ABUF;
#pragma unroll
        for (int t = 0; t < 2; t++) {
            int fidx = tid + t * 256;
            int m = fidx >> 2, kc = fidx & 3;
            cp16(smem_u32(&As[m * BB_STR + kc * 8]),
                 &A[(size_t)(m0 + m) * lda + k0 + kc * 8]);
        }
#pragma unroll
        for (int t = 0; t < 2; t++) {
            int fidx = tid + t * 256;
            int n = fidx >> 2, kc = fidx & 3;
            cp16(smem_u32(&Ws[n * BB_STR + kc * 8]),
                 &W[(size_t)(n0 + n) * K + k0 + kc * 8]);
        }
        asm volatile("cp.async.commit_group;");
    };

    float acc[4][4][4];
#pragma unroll
    for (int i = 0; i < 4; i++)
#pragma unroll
        for (int j = 0; j < 4; j++)
#pragma unroll
            for (int q = 0; q < 4; q++) acc[i][j][q] = 0.f;

    const int nit = K / 32;
    issue_tile(0, 0);
    if (nit > 1) issue_tile(1, 32);

    for (int it = 0; it < nit; it++) {
        if (it + 1 < nit) asm volatile("cp.async.wait_group 1;");
        else              asm volatile("cp.async.wait_group 0;");
        __syncthreads();
        if (it + 2 < nit) issue_tile((it + 2) % 3, (it + 2) * 32);

        const __nv_bfloat16* ab = dyn + (it % 3) * BB_STAGE;
        const __nv_bfloat16* wb = ab + BB_ABUF;
#pragma unroll
        for (int kk = 0; kk < 2; kk++) {
            const int kb = kk * 16;
            unsigned int a[4][4], b[4][2];
#pragma unroll
            for (int mf = 0; mf < 4; mf++) {
                int r = wm + mf * 16 + lq;
                a[mf][0] = *(const unsigned*)&ab[r * BB_STR + kb + lp * 2];
                a[mf][1] = *(const unsigned*)&ab[(r + 8) * BB_STR + kb + lp * 2];
                a[mf][2] = *(const unsigned*)&ab[r * BB_STR + kb + 8 + lp * 2];
                a[mf][3] = *(const unsigned*)&ab[(r + 8) * BB_STR + kb + 8 + lp * 2];
            }
#pragma unroll
            for (int nf = 0; nf < 4; nf++) {
                int n = wn + nf * 8 + lq;
                b[nf][0] = *(const unsigned*)&wb[n * BB_STR + kb + lp * 2];
                b[nf][1] = *(const unsigned*)&wb[n * BB_STR + kb + 8 + lp * 2];
            }
#pragma unroll
            for (int mf = 0; mf < 4; mf++)
#pragma unroll
                for (int nf = 0; nf < 4; nf++) {
                    asm volatile(
                        "mma.sync.aligned.m16n8k16.row.col.f32.bf16.bf16.f32 "
                        "{%0,%1,%2,%3},{%4,%5,%6,%7},{%8,%9},{%0,%1,%2,%3};"
                        : "+f"(acc[mf][nf][0]), "+f"(acc[mf][nf][1]),
                          "+f"(acc[mf][nf][2]), "+f"(acc[mf][nf][3])
                        : "r"(a[mf][0]), "r"(a[mf][1]), "r"(a[mf][2]), "r"(a[mf][3]),
                          "r"(b[nf][0]), "r"(b[nf][1]));
                }
        }
        __syncthreads();
    }

#pragma unroll
    for (int mf = 0; mf < 4; mf++) {
#pragma unroll
        for (int nf = 0; nf < 4; nf++) {
            int r0 = m0 + wm + mf * 16 + lq;
            int c0 = n0 + wn + nf * 8 + lp * 2;
            if (EPI == 0) {
                __nv_bfloat16* C = (__nv_bfloat16*)Cptr;
                *(__nv_bfloat162*)&C[(size_t)r0 * N + c0] =
                    __floats2bfloat162_rn(acc[mf][nf][0], acc[mf][nf][1]);
                *(__nv_bfloat162*)&C[(size_t)(r0 + 8) * N + c0] =
                    __floats2bfloat162_rn(acc[mf][nf][2], acc[mf][nf][3]);
            } else {
                float* C = (float*)Cptr;
                float2 v0 = make_float2(acc[mf][nf][0], acc[mf][nf][1]);
                float2 v1 = make_float2(acc[mf][nf][2], acc[mf][nf][3]);
                float2 r0v = *(const float2*)&res[(size_t)r0 * N + c0];
                float2 r1v = *(const float2*)&res[(size_t)(r0 + 8) * N + c0];
                float l0 = ls[c0], l1 = ls[c0 + 1];
                v0.x = r0v.x + l0 * v0.x; v0.y = r0v.y + l1 * v0.y;
                v1.x = r1v.x + l0 * v1.x; v1.y = r1v.y + l1 * v1.y;
                *(float2*)&C[(size_t)r0 * N + c0] = v0;
                *(float2*)&C[(size_t)(r0 + 8) * N + c0] = v1;
            }
        }
    }
}

// ============ x_proj bf16 GEMM: 64x64x32 tile (256 CTAs), double-buffered =======
#define XB_ABUF (64 * BB_STR)
#define GEMMX_SMEM (4 * XB_ABUF * 2)

template <int NVALID>
__global__ __launch_bounds__(256)
void gemm_bf_x(const __nv_bfloat16* __restrict__ A, int lda,
               const __nv_bfloat16* __restrict__ W,
               float* __restrict__ C,
               int N, int K) {
    extern __shared__ char smem_raw[];
    __nv_bfloat16* As = (__nv_bfloat16*)smem_raw;      // [2][64][40]
    __nv_bfloat16* Ws = As + 2 * XB_ABUF;              // [2][64][40]

    const int tid = threadIdx.x;
    const int warp = tid >> 5, lane = tid & 31;
    const int wm = (warp >> 1) * 16;                   // 4 warp rows of 16
    const int wn = (warp & 1) * 32;                    // 2 warp cols of 32
    const int m0 = blockIdx.y * 64, n0 = 0;
    const int lq = lane >> 2, lp = lane & 3;

    if (NVALID < 64) {
        for (int i = tid; i < 2 * XB_ABUF; i += 256) {
            int row = (i % XB_ABUF) / BB_STR;
            if (row >= NVALID) Ws[i] = __float2bfloat16(0.f);
        }
    }

    auto issue_tile = [&](int buf, int k0) {
        {
            int m = tid >> 2, kc = tid & 3;
            cp16(smem_u32(&As[buf * XB_ABUF + m * BB_STR + kc * 8]),
                 &A[(size_t)(m0 + m) * lda + k0 + kc * 8]);
        }
        {
            int n = tid >> 2, kc = tid & 3;
            if (NVALID == 64 || n < NVALID)
                cp16(smem_u32(&Ws[buf * XB_ABUF + n * BB_STR + kc * 8]),
                     &W[(size_t)(n0 + n) * K + k0 + kc * 8]);
        }
        asm volatile("cp.async.commit_group;");
    };

    float acc[4][4];
#pragma unroll
    for (int j = 0; j < 4; j++)
#pragma unroll
        for (int q = 0; q < 4; q++) acc[j][q] = 0.f;

    const int nit = K / 32;
    issue_tile(0, 0);

    for (int it = 0; it < nit; it++) {
        int buf = it & 1;
        if (it + 1 < nit) {
            issue_tile(buf ^ 1, (it + 1) * 32);
            asm volatile("cp.async.wait_group 1;");
        } else {
            asm volatile("cp.async.wait_group 0;");
        }
        __syncthreads();

        const __nv_bfloat16* ab = As + buf * XB_ABUF;
        const __nv_bfloat16* wb = Ws + buf * XB_ABUF;
#pragma unroll
        for (int kk = 0; kk < 2; kk++) {
            const int kb = kk * 16;
            unsigned int a[4], b[4][2];
            {
                int r = wm + lq;
                a[0] = *(const unsigned*)&ab[r * BB_STR + kb + lp * 2];
                a[1] = *(const unsigned*)&ab[(r + 8) * BB_STR + kb + lp * 2];
                a[2] = *(const unsigned*)&ab[r * BB_STR + kb + 8 + lp * 2];
                a[3] = *(const unsigned*)&ab[(r + 8) * BB_STR + kb + 8 + lp * 2];
            }
#pragma unroll
            for (int nf = 0; nf < 4; nf++) {
                int n = wn + nf * 8 + lq;
                b[nf][0] = *(const unsigned*)&wb[n * BB_STR + kb + lp * 2];
                b[nf][1] = *(const unsigned*)&wb[n * BB_STR + kb + 8 + lp * 2];
            }
#pragma unroll
            for (int nf = 0; nf < 4; nf++) {
                asm volatile(
                    "mma.sync.aligned.m16n8k16.row.col.f32.bf16.bf16.f32 "
                    "{%0,%1,%2,%3},{%4,%5,%6,%7},{%8,%9},{%0,%1,%2,%3};"
                    : "+f"(acc[nf][0]), "+f"(acc[nf][1]),
                      "+f"(acc[nf][2]), "+f"(acc[nf][3])
                    : "r"(a[0]), "r"(a[1]), "r"(a[2]), "r"(a[3]),
                      "r"(b[nf][0]), "r"(b[nf][1]));
            }
        }
        __syncthreads();
    }

#pragma unroll
    for (int nf = 0; nf < 4; nf++) {
        int r0 = m0 + wm + lq;
        int c0 = n0 + wn + nf * 8 + lp * 2;
        if (NVALID < 64 && c0 >= NVALID) continue;
        *(float2*)&C[(size_t)r0 * N + c0] = make_float2(acc[nf][0], acc[nf][1]);
        *(float2*)&C[(size_t)(r0 + 8) * N + c0] = make_float2(acc[nf][2], acc[nf][3]);
    }
}

// -------- causal depthwise conv(4) + bias + SiLU: 4 timesteps per thread --------
__global__ void conv_silu_kernel(const float* __restrict__ cw,
                                 const float* __restrict__ cb) {
    int idx = blockIdx.x * 256 + threadIdx.x;    // over NTOK*DI/4
    int d = idx & (DI - 1);
    int g = idx >> 9;                            // 4-token group
    int n0 = g << 2;
    int l0 = n0 & (SEQ - 1);

    float w0 = cw[d * 4 + 0], w1 = cw[d * 4 + 1];
    float w2 = cw[d * 4 + 2], w3 = cw[d * 4 + 3];
    float bias = cb[d];

    float xv[7];
#pragma unroll
    for (int j = 0; j < 7; j++) {
        int ll = l0 - 3 + j;
        xv[j] = (ll >= 0)
            ? __bfloat162float(g_xzbf[(size_t)(n0 - 3 + j) * (2 * DI) + d])
            : 0.f;
    }

#pragma unroll
    for (int t = 0; t < 4; t++) {
        float acc = bias;
        acc = fmaf(w0, xv[t + 0], acc);
        acc = fmaf(w1, xv[t + 1], acc);
        acc = fmaf(w2, xv[t + 2], acc);
        acc = fmaf(w3, xv[t + 3], acc);
        float su = acc * sigmoidf_(acc);
        g_ubf[(size_t)(n0 + t) * DI + d] = __float2bfloat16(su);
    }
}

// ---------------- selective scan: double-buffered stage, 2 syncs/chunk ----------
// block = 256 threads = 16 channels x 16 states; TCH=32 steps per chunk.
// Iteration: issue next-chunk LDGs -> compute dt -> sync -> recurrence+reduce
// (two 16-step halves, warp-local transpose) -> stage regs to alt buffer -> sync.
#define TCH 32
__global__ __launch_bounds__(256)
void scan_kernel(const float* __restrict__ A_log,
                 const float* __restrict__ Dp,
                 const float* __restrict__ dtw,   // [DI,16]
                 const float* __restrict__ dtb) { // [DI]
    __shared__ float sx[2][TCH * 48];
    __shared__ float su_[2][TCH][17], sz_[2][TCH][17];
    __shared__ float sdt_[TCH][17];
    __shared__ float sdtw[16][17];
    __shared__ float sp[8][16][33];

    int tid = threadIdx.x;
    int ch = tid >> 4;                // channel within block (0..15)
    int s = tid & 15;                 // state index
    int w = tid >> 5;                 // warp (channels 2w, 2w+1)
    int lane = tid & 31;
    int b = blockIdx.x >> 5;
    int d0 = (blockIdx.x & 31) << 4;
    int d = d0 + ch;

    int lt = tid >> 4, lj = tid & 15; // staging/compute role

    sdtw[s][ch] = dtw[(d0 + ch) * 16 + s];
    float dtb_j = dtb[d0 + lj];

    float As = -__expf(A_log[d * DS + s]);
    float h = 0.f;
    size_t base = (size_t)b * SEQ;

    // phase-2 role: lane -> (timestep t2 within half, channel c of warp's pair)
    int t2 = lane >> 1, c2 = lane & 1;
    int cB = 2 * w + c2;
    float Dv2 = Dp[d0 + cB];

    float p_x[6], p_u0, p_u1, p_z0, p_z1;

    // stage chunk 0 into buffer 0
    {
        const float* xrow = g_xdbl + base * 48;
#pragma unroll
        for (int i = 0; i < 6; i++) sx[0][tid + i * 256] = xrow[tid + i * 256];
        su_[0][lt][lj]      = __bfloat162float(g_ubf[(base + lt) * DI + d0 + lj]);
        su_[0][lt + 16][lj] = __bfloat162float(g_ubf[(base + lt + 16) * DI + d0 + lj]);
        sz_[0][lt][lj]      = __bfloat162float(g_xzbf[(base + lt) * (2 * DI) + DI + d0 + lj]);
        sz_[0][lt + 16][lj] = __bfloat162float(g_xzbf[(base + lt + 16) * (2 * DI) + DI + d0 + lj]);
    }
    __syncthreads();

    const int nchunks = SEQ / TCH;
    for (int ic = 0; ic < nchunks; ic++) {
        int buf = ic & 1;
        int l0 = ic * TCH;

        // issue next chunk's loads early (latency hidden by dt + recurrence)
        if (ic + 1 < nchunks) {
            const float* xrow = g_xdbl + (base + l0 + TCH) * 48;
#pragma unroll
            for (int i = 0; i < 6; i++) p_x[i] = xrow[tid + i * 256];
            size_t n = base + l0 + TCH + lt;
            p_u0 = __bfloat162float(g_ubf[n * DI + d0 + lj]);
            p_u1 = __bfloat162float(g_ubf[(n + 16) * DI + d0 + lj]);
            p_z0 = __bfloat162float(g_xzbf[n * (2 * DI) + DI + d0 + lj]);
            p_z1 = __bfloat162float(g_xzbf[(n + 16) * (2 * DI) + DI + d0 + lj]);
        }

        // fused dt_proj + softplus for this chunk
        {
            float v0 = dtb_j, v1 = dtb_j;
#pragma unroll
            for (int r = 0; r < 16; r++) {
                float wv = sdtw[r][lj];
                v0 = fmaf(sx[buf][lt * 48 + r], wv, v0);
                v1 = fmaf(sx[buf][(lt + 16) * 48 + r], wv, v1);
            }
            sdt_[lt][lj]      = (v0 > 20.f) ? v0 : log1pf(__expf(v0));
            sdt_[lt + 16][lj] = (v1 > 20.f) ? v1 : log1pf(__expf(v1));
        }
        __syncthreads();   // sdt ready

        // two 16-step halves: recurrence -> warp transpose -> reduce
#pragma unroll
        for (int hc = 0; hc < 2; hc++) {
#pragma unroll
            for (int t = 0; t < 16; t++) {
                int tt = hc * 16 + t;
                float r  = sdt_[tt][ch];
                float uu = su_[buf][tt][ch];
                float dA = __expf(r * As);
                h = fmaf(dA, h, (r * uu) * sx[buf][tt * 48 + 16 + s]);
                sp[w][t][lane] = h * sx[buf][tt * 48 + 32 + s];
            }
            __syncwarp();
            float a = 0.f;
#pragma unroll
            for (int k = 0; k < 16; k++) a += sp[w][t2][c2 * 16 + k];
            int tt2 = hc * 16 + t2;
            float uu2 = su_[buf][tt2][cB];
            float zz  = sz_[buf][tt2][cB];
            g_ybf[(base + l0 + tt2) * DI + d0 + cB] =
                __float2bfloat16((a + uu2 * Dv2) * (zz * sigmoidf_(zz)));
            __syncwarp();  // sp consumed before next half overwrites
        }

        // stage next chunk into alternate buffer
        if (ic + 1 < nchunks) {
#pragma unroll
            for (int i = 0; i < 6; i++) sx[buf ^ 1][tid + i * 256] = p_x[i];
            su_[buf ^ 1][lt][lj] = p_u0; su_[buf ^ 1][lt + 16][lj] = p_u1;
            sz_[buf ^ 1][lt][lj] = p_z0; sz_[buf ^ 1][lt + 16][lj] = p_z1;
        }
        __syncthreads();   // staging visible; sdt free to overwrite
    }
}

// ---------------- host orchestration --------------------------------------------
extern "C" void kernel_launch(void* const* d_in, const int* in_sizes, int n_in,
                              void* d_out, int out_size) {
    const float* x    = (const float*)d_in[0];
    const float* ln_g = (const float*)d_in[1];
    const float* ln_b = (const float*)d_in[2];
    const float* inw  = (const float*)d_in[3];   // [2,1024,256]
    const float* cw   = (const float*)d_in[4];   // [2,512,4]
    const float* cb   = (const float*)d_in[5];   // [2,512]
    const float* xpw  = (const float*)d_in[6];   // [2,48,512]
    const float* dtw  = (const float*)d_in[7];   // [2,512,16]
    const float* dtb  = (const float*)d_in[8];   // [2,512]
    const float* alog = (const float*)d_in[9];   // [2,512,16]
    const float* dp   = (const float*)d_in[10];  // [2,512]
    const float* ow   = (const float*)d_in[11];  // [2,256,512]
    const float* ls   = (const float*)d_in[12];  // [2,256]
    float* out = (float*)d_out;

    cudaFuncSetAttribute(gemm_bf_big<0>, cudaFuncAttributeMaxDynamicSharedMemorySize, GEMMB_SMEM);
    cudaFuncSetAttribute(gemm_bf_big<1>, cudaFuncAttributeMaxDynamicSharedMemorySize, GEMMB_SMEM);
    cudaFuncSetAttribute(gemm_bf_x<48>, cudaFuncAttributeMaxDynamicSharedMemorySize, GEMMX_SMEM);

    __nv_bfloat16 *p_lnbf, *p_xzbf, *p_ubf, *p_ybf, *p_wbf;
    float *p_xdbl;
    cudaGetSymbolAddress((void**)&p_lnbf, g_lnbf);
    cudaGetSymbolAddress((void**)&p_xzbf, g_xzbf);
    cudaGetSymbolAddress((void**)&p_ubf,  g_ubf);
    cudaGetSymbolAddress((void**)&p_xdbl, g_xdbl);
    cudaGetSymbolAddress((void**)&p_ybf,  g_ybf);
    cudaGetSymbolAddress((void**)&p_wbf,  g_wbf);

    // 0) weight conversion (both layers)
    convert_weights<<<(2 * W_LAYER + 255) / 256, 256>>>(inw, xpw, ow);

    for (int i = 0; i < 2; i++) {
        const float* xin = (i == 0) ? x : out;
        const __nv_bfloat16* wl = p_wbf + (size_t)i * W_LAYER;

        // 1) layernorm (-> bf16)
        ln_kernel<<<NTOK / 8, 256>>>(xin, ln_g + i * DM, ln_b + i * DM);

        // 2) in_proj: [N,256] x [1024,256]^T -> [N,1024] bf16  (mma, 3-stage)
        gemm_bf_big<0><<<dim3((2 * DI) / 128, NTOK / 128), 256, GEMMB_SMEM>>>(
            p_lnbf, DM, wl, p_xzbf, 2 * DI, DM, nullptr, nullptr);

        // 3) causal conv4 + bias + SiLU (bf16 in/out, 4 timesteps/thread)
        conv_silu_kernel<<<(NTOK * DI / 4) / 256, 256>>>(cw + i * DI * 4, cb + i * DI);

        // 4) x_proj: [N,512] x [48,512]^T -> [N,48]  (bf16 mma, 64-row tiles)
        gemm_bf_x<48><<<dim3(1, NTOK / 64), 256, GEMMX_SMEM>>>(
            p_ubf, DI, wl + W_XP_OFF, p_xdbl, 48, DI);

        // 5) selective scan with fused dt_proj + D skip + z gating (-> bf16 y)
        scan_kernel<<<(BATCH * DI) / 16, 256>>>(
            alog + (size_t)i * DI * DS, dp + i * DI,
            dtw + (size_t)i * DI * 16, dtb + i * DI);

        // 6) out_proj fused with residual + layer_scale: out = xin + ls * (y @ ow^T)
        gemm_bf_big<1><<<dim3(DM / 128, NTOK / 128), 256, GEMMB_SMEM>>>(
            p_ybf, DI, wl + W_OW_OFF, out, DM, DI, xin, ls + i * DM);
    }
}

// round 15
// speedup vs baseline: 1.0350x; 1.0350x over previous
#include <cuda_runtime.h>
#include <cuda_bf16.h>
#include <stdint.h>
#include <math.h>

#define NTOK  16384
#define BATCH 8
#define SEQ   2048
#define DM    256
#define DI    512
#define DS    16

// weight scratch layout per layer: [inw 1024*256 | xpw 48*512 | ow 256*512]
#define W_INP_SZ (1024 * 256)
#define W_XP_OFF W_INP_SZ
#define W_XP_SZ  (48 * 512)
#define W_OW_OFF (W_XP_OFF + W_XP_SZ)
#define W_OW_SZ  (256 * 512)
#define W_LAYER  (W_OW_OFF + W_OW_SZ)

// ---------------- scratch (allocation-free: __device__ globals) ----------------
__device__ __nv_bfloat16 g_lnbf[NTOK * DM];     // layernorm output (bf16)
__device__ __nv_bfloat16 g_xzbf[NTOK * 2 * DI]; // in_proj output (u | z) bf16
__device__ __nv_bfloat16 g_ubf[NTOK * DI];      // conv+silu output (bf16)
__device__ float         g_xdbl[NTOK * 48];     // x_proj output (dt_r | B | C)
__device__ __nv_bfloat16 g_ybf[NTOK * DI];      // scan output, gated (bf16)
__device__ __nv_bfloat16 g_wbf[2 * W_LAYER];    // bf16 weights

__device__ __forceinline__ float sigmoidf_(float v) { return 1.f / (1.f + __expf(-v)); }

__device__ __forceinline__ unsigned smem_u32(const void* p) {
    return (unsigned)__cvta_generic_to_shared(p);
}
__device__ __forceinline__ void cp16(unsigned dst, const void* src) {
    asm volatile("cp.async.cg.shared.global [%0], [%1], 16;" :: "r"(dst), "l"(src));
}

// ---------------- one-shot weight conversion fp32 -> bf16 -----------------------
__global__ void convert_weights(const float* __restrict__ inw,
                                const float* __restrict__ xpw,
                                const float* __restrict__ ow) {
    int idx = blockIdx.x * 256 + threadIdx.x;
    if (idx >= 2 * W_LAYER) return;
    int layer = idx / W_LAYER, r = idx % W_LAYER;
    float v;
    if (r < W_INP_SZ)       v = inw[(size_t)layer * W_INP_SZ + r];
    else if (r < W_OW_OFF)  v = xpw[(size_t)layer * W_XP_SZ + (r - W_XP_OFF)];
    else                    v = ow[(size_t)layer * W_OW_SZ + (r - W_OW_OFF)];
    g_wbf[idx] = __float2bfloat16(v);
}

// ---------------- layernorm: one warp per token, writes bf16 --------------------
__global__ void ln_kernel(const float* __restrict__ x,
                          const float* __restrict__ g,
                          const float* __restrict__ b) {
    int warp = threadIdx.x >> 5, lane = threadIdx.x & 31;
    int tok = blockIdx.x * 8 + warp;
    const float* row = x + (size_t)tok * DM;
    float v[8];
    float s = 0.f, s2 = 0.f;
#pragma unroll
    for (int i = 0; i < 8; i++) {
        v[i] = row[lane + i * 32];
        s += v[i];
        s2 += v[i] * v[i];
    }
#pragma unroll
    for (int o = 16; o; o >>= 1) {
        s  += __shfl_xor_sync(0xffffffffu, s, o);
        s2 += __shfl_xor_sync(0xffffffffu, s2, o);
    }
    float m   = s * (1.f / DM);
    float var = s2 * (1.f / DM) - m * m;
    float inv = rsqrtf(var + 1e-5f);
    __nv_bfloat16* o = g_lnbf + (size_t)tok * DM;
#pragma unroll
    for (int i = 0; i < 8; i++) {
        int c = lane + i * 32;
        o[c] = __float2bfloat16((v[i] - m) * inv * g[c] + b[c]);
    }
}

// ============ BIG bf16 GEMM: 128x128x32, m16n8k16, 4-stage cp.async =============
// EPI 0: C is bf16 (plain store). EPI 1: C is fp32, res + ls[n]*acc.
#define BB_STR  40
#define BB_ABUF (128 * BB_STR)
#define BB_STAGE (2 * BB_ABUF)
#define GEMMB_SMEM (4 * BB_STAGE * 2)

template <int EPI>
__global__ __launch_bounds__(256)
void gemm_bf_big(const __nv_bfloat16* __restrict__ A, int lda,
                 const __nv_bfloat16* __restrict__ W,
                 void* __restrict__ Cptr,
                 int N, int K,
                 const float* __restrict__ res,
                 const float* __restrict__ ls) {
    extern __shared__ char smem_raw[];
    __nv_bfloat16* dyn = (__nv_bfloat16*)smem_raw;

    const int tid = threadIdx.x;
    const int warp = tid >> 5, lane = tid & 31;
    const int wm = (warp >> 2) * 64;
    const int wn = (warp & 3) * 32;
    const int m0 = blockIdx.y * 128, n0 = blockIdx.x * 128;
    const int lq = lane >> 2, lp = lane & 3;

    auto issue_tile = [&](int st, int k0) {
        __nv_bfloat16* As = dyn + st * BB_STAGE;
        __nv_bfloat16* Ws = As + BB_ABUF;
#pragma unroll
        for (int t = 0; t < 2; t++) {
            int fidx = tid + t * 256;
            int m = fidx >> 2, kc = fidx & 3;
            cp16(smem_u32(&As[m * BB_STR + kc * 8]),
                 &A[(size_t)(m0 + m) * lda + k0 + kc * 8]);
        }
#pragma unroll
        for (int t = 0; t < 2; t++) {
            int fidx = tid + t * 256;
            int n = fidx >> 2, kc = fidx & 3;
            cp16(smem_u32(&Ws[n * BB_STR + kc * 8]),
                 &W[(size_t)(n0 + n) * K + k0 + kc * 8]);
        }
        asm volatile("cp.async.commit_group;");
    };

    float acc[4][4][4];
#pragma unroll
    for (int i = 0; i < 4; i++)
#pragma unroll
        for (int j = 0; j < 4; j++)
#pragma unroll
            for (int q = 0; q < 4; q++) acc[i][j][q] = 0.f;

    const int nit = K / 32;
    issue_tile(0, 0);
    if (nit > 1) issue_tile(1, 32);
    if (nit > 2) issue_tile(2, 64);

    for (int it = 0; it < nit; it++) {
        if (it + 1 < nit) {
            if (it + 2 < nit) asm volatile("cp.async.wait_group 2;");
            else              asm volatile("cp.async.wait_group 1;");
        } else {
            asm volatile("cp.async.wait_group 0;");
        }
        __syncthreads();
        if (it + 3 < nit) issue_tile((it + 3) & 3, (it + 3) * 32);

        const __nv_bfloat16* ab = dyn + (it & 3) * BB_STAGE;
        const __nv_bfloat16* wb = ab + BB_ABUF;
#pragma unroll
        for (int kk = 0; kk < 2; kk++) {
            const int kb = kk * 16;
            unsigned int a[4][4], b[4][2];
#pragma unroll
            for (int mf = 0; mf < 4; mf++) {
                int r = wm + mf * 16 + lq;
                a[mf][0] = *(const unsigned*)&ab[r * BB_STR + kb + lp * 2];
                a[mf][1] = *(const unsigned*)&ab[(r + 8) * BB_STR + kb + lp * 2];
                a[mf][2] = *(const unsigned*)&ab[r * BB_STR + kb + 8 + lp * 2];
                a[mf][3] = *(const unsigned*)&ab[(r + 8) * BB_STR + kb + 8 + lp * 2];
            }
#pragma unroll
            for (int nf = 0; nf < 4; nf++) {
                int n = wn + nf * 8 + lq;
                b[nf][0] = *(const unsigned*)&wb[n * BB_STR + kb + lp * 2];
                b[nf][1] = *(const unsigned*)&wb[n * BB_STR + kb + 8 + lp * 2];
            }
#pragma unroll
            for (int mf = 0; mf < 4; mf++)
#pragma unroll
                for (int nf = 0; nf < 4; nf++) {
                    asm volatile(
                        "mma.sync.aligned.m16n8k16.row.col.f32.bf16.bf16.f32 "
                        "{%0,%1,%2,%3},{%4,%5,%6,%7},{%8,%9},{%0,%1,%2,%3};"
                        : "+f"(acc[mf][nf][0]), "+f"(acc[mf][nf][1]),
                          "+f"(acc[mf][nf][2]), "+f"(acc[mf][nf][3])
                        : "r"(a[mf][0]), "r"(a[mf][1]), "r"(a[mf][2]), "r"(a[mf][3]),
                          "r"(b[nf][0]), "r"(b[nf][1]));
                }
        }
        __syncthreads();
    }

#pragma unroll
    for (int mf = 0; mf < 4; mf++) {
#pragma unroll
        for (int nf = 0; nf < 4; nf++) {
            int r0 = m0 + wm + mf * 16 + lq;
            int c0 = n0 + wn + nf * 8 + lp * 2;
            if (EPI == 0) {
                __nv_bfloat16* C = (__nv_bfloat16*)Cptr;
                *(__nv_bfloat162*)&C[(size_t)r0 * N + c0] =
                    __floats2bfloat162_rn(acc[mf][nf][0], acc[mf][nf][1]);
                *(__nv_bfloat162*)&C[(size_t)(r0 + 8) * N + c0] =
                    __floats2bfloat162_rn(acc[mf][nf][2], acc[mf][nf][3]);
            } else {
                float* C = (float*)Cptr;
                float2 v0 = make_float2(acc[mf][nf][0], acc[mf][nf][1]);
                float2 v1 = make_float2(acc[mf][nf][2], acc[mf][nf][3]);
                float2 r0v = *(const float2*)&res[(size_t)r0 * N + c0];
                float2 r1v = *(const float2*)&res[(size_t)(r0 + 8) * N + c0];
                float l0 = ls[c0], l1 = ls[c0 + 1];
                v0.x = r0v.x + l0 * v0.x; v0.y = r0v.y + l1 * v0.y;
                v1.x = r1v.x + l0 * v1.x; v1.y = r1v.y + l1 * v1.y;
                *(float2*)&C[(size_t)r0 * N + c0] = v0;
                *(float2*)&C[(size_t)(r0 + 8) * N + c0] = v1;
            }
        }
    }
}

// ============ narrow bf16 GEMM (x_proj): 128x64x32, double-buffered =============
#define NB_ABUF (128 * BB_STR)
#define NB_WBUF (64 * BB_STR)
#define GEMMN_SMEM ((2 * NB_ABUF + 2 * NB_WBUF) * 2)

template <int NVALID>
__global__ __launch_bounds__(256)
void gemm_bf_narrow(const __nv_bfloat16* __restrict__ A, int lda,
                    const __nv_bfloat16* __restrict__ W,
                    float* __restrict__ C,
                    int N, int K) {
    extern __shared__ char smem_raw[];
    __nv_bfloat16* As = (__nv_bfloat16*)smem_raw;
    __nv_bfloat16* Ws = As + 2 * NB_ABUF;

    const int tid = threadIdx.x;
    const int warp = tid >> 5, lane = tid & 31;
    const int wm = (warp >> 1) * 32;
    const int wn = (warp & 1) * 32;
    const int m0 = blockIdx.y * 128, n0 = blockIdx.x * 64;
    const int lq = lane >> 2, lp = lane & 3;

    if (NVALID < 64) {
        for (int i = tid; i < 2 * NB_WBUF; i += 256) {
            int row = (i % NB_WBUF) / BB_STR;
            if (row >= NVALID) Ws[i] = __float2bfloat16(0.f);
        }
    }

    auto issue_tile = [&](int buf, int k0) {
#pragma unroll
        for (int t = 0; t < 2; t++) {
            int fidx = tid + t * 256;
            int m = fidx >> 2, kc = fidx & 3;
            cp16(smem_u32(&As[buf * NB_ABUF + m * BB_STR + kc * 8]),
                 &A[(size_t)(m0 + m) * lda + k0 + kc * 8]);
        }
        {
            int n = tid >> 2, kc = tid & 3;
            if (NVALID == 64 || n < NVALID)
                cp16(smem_u32(&Ws[buf * NB_WBUF + n * BB_STR + kc * 8]),
                     &W[(size_t)(n0 + n) * K + k0 + kc * 8]);
        }
        asm volatile("cp.async.commit_group;");
    };

    float acc[2][4][4];
#pragma unroll
    for (int i = 0; i < 2; i++)
#pragma unroll
        for (int j = 0; j < 4; j++)
#pragma unroll
            for (int q = 0; q < 4; q++) acc[i][j][q] = 0.f;

    const int nit = K / 32;
    issue_tile(0, 0);

    for (int it = 0; it < nit; it++) {
        int buf = it & 1;
        if (it + 1 < nit) {
            issue_tile(buf ^ 1, (it + 1) * 32);
            asm volatile("cp.async.wait_group 1;");
        } else {
            asm volatile("cp.async.wait_group 0;");
        }
        __syncthreads();

        const __nv_bfloat16* ab = As + buf * NB_ABUF;
        const __nv_bfloat16* wb = Ws + buf * NB_WBUF;
#pragma unroll
        for (int kk = 0; kk < 2; kk++) {
            const int kb = kk * 16;
            unsigned int a[2][4], b[4][2];
#pragma unroll
            for (int mf = 0; mf < 2; mf++) {
                int r = wm + mf * 16 + lq;
                a[mf][0] = *(const unsigned*)&ab[r * BB_STR + kb + lp * 2];
                a[mf][1] = *(const unsigned*)&ab[(r + 8) * BB_STR + kb + lp * 2];
                a[mf][2] = *(const unsigned*)&ab[r * BB_STR + kb + 8 + lp * 2];
                a[mf][3] = *(const unsigned*)&ab[(r + 8) * BB_STR + kb + 8 + lp * 2];
            }
#pragma unroll
            for (int nf = 0; nf < 4; nf++) {
                int n = wn + nf * 8 + lq;
                b[nf][0] = *(const unsigned*)&wb[n * BB_STR + kb + lp * 2];
                b[nf][1] = *(const unsigned*)&wb[n * BB_STR + kb + 8 + lp * 2];
            }
#pragma unroll
            for (int mf = 0; mf < 2; mf++)
#pragma unroll
                for (int nf = 0; nf < 4; nf++) {
                    asm volatile(
                        "mma.sync.aligned.m16n8k16.row.col.f32.bf16.bf16.f32 "
                        "{%0,%1,%2,%3},{%4,%5,%6,%7},{%8,%9},{%0,%1,%2,%3};"
                        : "+f"(acc[mf][nf][0]), "+f"(acc[mf][nf][1]),
                          "+f"(acc[mf][nf][2]), "+f"(acc[mf][nf][3])
                        : "r"(a[mf][0]), "r"(a[mf][1]), "r"(a[mf][2]), "r"(a[mf][3]),
                          "r"(b[nf][0]), "r"(b[nf][1]));
                }
        }
        __syncthreads();
    }

#pragma unroll
    for (int mf = 0; mf < 2; mf++) {
#pragma unroll
        for (int nf = 0; nf < 4; nf++) {
            int r0 = m0 + wm + mf * 16 + lq;
            int c0 = n0 + wn + nf * 8 + lp * 2;
            if (NVALID < 64 && c0 >= NVALID) continue;
            float2 v0 = make_float2(acc[mf][nf][0], acc[mf][nf][1]);
            float2 v1 = make_float2(acc[mf][nf][2], acc[mf][nf][3]);
            *(float2*)&C[(size_t)r0 * N + c0] = v0;
            *(float2*)&C[(size_t)(r0 + 8) * N + c0] = v1;
        }
    }
}

// -------- causal depthwise conv(4) + bias + SiLU: 4 timesteps per thread --------
__global__ void conv_silu_kernel(const float* __restrict__ cw,
                                 const float* __restrict__ cb) {
    int idx = blockIdx.x * 256 + threadIdx.x;    // over NTOK*DI/4
    int d = idx & (DI - 1);
    int g = idx >> 9;                            // 4-token group
    int n0 = g << 2;
    int l0 = n0 & (SEQ - 1);

    float w0 = cw[d * 4 + 0], w1 = cw[d * 4 + 1];
    float w2 = cw[d * 4 + 2], w3 = cw[d * 4 + 3];
    float bias = cb[d];

    float xv[7];
#pragma unroll
    for (int j = 0; j < 7; j++) {
        int ll = l0 - 3 + j;
        xv[j] = (ll >= 0)
            ? __bfloat162float(g_xzbf[(size_t)(n0 - 3 + j) * (2 * DI) + d])
            : 0.f;
    }

#pragma unroll
    for (int t = 0; t < 4; t++) {
        float acc = bias;
        acc = fmaf(w0, xv[t + 0], acc);
        acc = fmaf(w1, xv[t + 1], acc);
        acc = fmaf(w2, xv[t + 2], acc);
        acc = fmaf(w3, xv[t + 3], acc);
        float su = acc * sigmoidf_(acc);
        g_ubf[(size_t)(n0 + t) * DI + d] = __float2bfloat16(su);
    }
}

// ---------------- selective scan: shuffle-free, TCH=32 chunks (R13) -------------
#define TCH 32
__global__ __launch_bounds__(256)
void scan_kernel(const float* __restrict__ A_log,
                 const float* __restrict__ Dp,
                 const float* __restrict__ dtw,   // [DI,16]
                 const float* __restrict__ dtb) { // [DI]
    __shared__ float sx[TCH * 48];
    __shared__ float su_[TCH][17], sz_[TCH][17], sdt_[TCH][17];
    __shared__ float sdtw[16][17];
    __shared__ float sp[8][TCH][33];

    int tid = threadIdx.x;
    int ch = tid >> 4;
    int s = tid & 15;
    int w = tid >> 5;
    int lane = tid & 31;
    int b = blockIdx.x >> 5;
    int d0 = (blockIdx.x & 31) << 4;
    int d = d0 + ch;

    int lt = tid >> 4, lj = tid & 15;

    sdtw[s][ch] = dtw[(d0 + ch) * 16 + s];
    float dtb_j = dtb[d0 + lj];

    float As = -__expf(A_log[d * DS + s]);
    float h = 0.f;
    size_t base = (size_t)b * SEQ;

    float Dv0 = Dp[d0 + 2 * w], Dv1 = Dp[d0 + 2 * w + 1];

    float p_x[6], p_u0, p_u1, p_z0, p_z1;
    {
        const float* xrow = g_xdbl + base * 48;
#pragma unroll
        for (int i = 0; i < 6; i++) p_x[i] = xrow[tid + i * 256];
        p_u0 = __bfloat162float(g_ubf[(base + lt) * DI + d0 + lj]);
        p_u1 = __bfloat162float(g_ubf[(base + lt + 16) * DI + d0 + lj]);
        p_z0 = __bfloat162float(g_xzbf[(base + lt) * (2 * DI) + DI + d0 + lj]);
        p_z1 = __bfloat162float(g_xzbf[(base + lt + 16) * (2 * DI) + DI + d0 + lj]);
    }

    for (int l0 = 0; l0 < SEQ; l0 += TCH) {
        __syncthreads();
#pragma unroll
        for (int i = 0; i < 6; i++) sx[tid + i * 256] = p_x[i];
        su_[lt][lj] = p_u0; su_[lt + 16][lj] = p_u1;
        sz_[lt][lj] = p_z0; sz_[lt + 16][lj] = p_z1;
        __syncthreads();

        {
            float v0 = dtb_j, v1 = dtb_j;
#pragma unroll
            for (int r = 0; r < 16; r++) {
                float wv = sdtw[r][lj];
                v0 = fmaf(sx[lt * 48 + r], wv, v0);
                v1 = fmaf(sx[(lt + 16) * 48 + r], wv, v1);
            }
            sdt_[lt][lj]      = (v0 > 20.f) ? v0 : log1pf(__expf(v0));
            sdt_[lt + 16][lj] = (v1 > 20.f) ? v1 : log1pf(__expf(v1));
        }

        if (l0 + TCH < SEQ) {
            const float* xrow = g_xdbl + (base + l0 + TCH) * 48;
#pragma unroll
            for (int i = 0; i < 6; i++) p_x[i] = xrow[tid + i * 256];
            size_t n = base + l0 + TCH + lt;
            p_u0 = __bfloat162float(g_ubf[n * DI + d0 + lj]);
            p_u1 = __bfloat162float(g_ubf[(n + 16) * DI + d0 + lj]);
            p_z0 = __bfloat162float(g_xzbf[n * (2 * DI) + DI + d0 + lj]);
            p_z1 = __bfloat162float(g_xzbf[(n + 16) * (2 * DI) + DI + d0 + lj]);
        }
        __syncthreads();

        // ---- phase 1: recurrence, h*C straight to transpose buffer ----
#pragma unroll
        for (int t = 0; t < TCH; t++) {
            float r  = sdt_[t][ch];
            float uu = su_[t][ch];
            float dA = __expf(r * As);
            h = fmaf(dA, h, (r * uu) * sx[t * 48 + 16 + s]);
            sp[w][t][lane] = h * sx[t * 48 + 32 + s];
        }
        __syncwarp();

        // ---- phase 2: lane t sums 16 states for the warp's 2 channels ----
        float a0 = 0.f, a1 = 0.f;
#pragma unroll
        for (int k = 0; k < 16; k++) {
            a0 += sp[w][lane][k];
            a1 += sp[w][lane][16 + k];
        }
        float uu0 = su_[lane][2 * w],     zz0 = sz_[lane][2 * w];
        float uu1 = su_[lane][2 * w + 1], zz1 = sz_[lane][2 * w + 1];
        float y0 = (a0 + uu0 * Dv0) * (zz0 * sigmoidf_(zz0));
        float y1 = (a1 + uu1 * Dv1) * (zz1 * sigmoidf_(zz1));
        *(__nv_bfloat162*)&g_ybf[(base + l0 + lane) * DI + d0 + 2 * w] =
            __floats2bfloat162_rn(y0, y1);
    }
}

// ---------------- host orchestration --------------------------------------------
extern "C" void kernel_launch(void* const* d_in, const int* in_sizes, int n_in,
                              void* d_out, int out_size) {
    const float* x    = (const float*)d_in[0];
    const float* ln_g = (const float*)d_in[1];
    const float* ln_b = (const float*)d_in[2];
    const float* inw  = (const float*)d_in[3];   // [2,1024,256]
    const float* cw   = (const float*)d_in[4];   // [2,512,4]
    const float* cb   = (const float*)d_in[5];   // [2,512]
    const float* xpw  = (const float*)d_in[6];   // [2,48,512]
    const float* dtw  = (const float*)d_in[7];   // [2,512,16]
    const float* dtb  = (const float*)d_in[8];   // [2,512]
    const float* alog = (const float*)d_in[9];   // [2,512,16]
    const float* dp   = (const float*)d_in[10];  // [2,512]
    const float* ow   = (const float*)d_in[11];  // [2,256,512]
    const float* ls   = (const float*)d_in[12];  // [2,256]
    float* out = (float*)d_out;

    cudaFuncSetAttribute(gemm_bf_big<0>, cudaFuncAttributeMaxDynamicSharedMemorySize, GEMMB_SMEM);
    cudaFuncSetAttribute(gemm_bf_big<1>, cudaFuncAttributeMaxDynamicSharedMemorySize, GEMMB_SMEM);
    cudaFuncSetAttribute(gemm_bf_narrow<48>, cudaFuncAttributeMaxDynamicSharedMemorySize, GEMMN_SMEM);

    __nv_bfloat16 *p_lnbf, *p_xzbf, *p_ubf, *p_ybf, *p_wbf;
    float *p_xdbl;
    cudaGetSymbolAddress((void**)&p_lnbf, g_lnbf);
    cudaGetSymbolAddress((void**)&p_xzbf, g_xzbf);
    cudaGetSymbolAddress((void**)&p_ubf,  g_ubf);
    cudaGetSymbolAddress((void**)&p_xdbl, g_xdbl);
    cudaGetSymbolAddress((void**)&p_ybf,  g_ybf);
    cudaGetSymbolAddress((void**)&p_wbf,  g_wbf);

    // 0) weight conversion (both layers)
    convert_weights<<<(2 * W_LAYER + 255) / 256, 256>>>(inw, xpw, ow);

    for (int i = 0; i < 2; i++) {
        const float* xin = (i == 0) ? x : out;
        const __nv_bfloat16* wl = p_wbf + (size_t)i * W_LAYER;

        // 1) layernorm (-> bf16)
        ln_kernel<<<NTOK / 8, 256>>>(xin, ln_g + i * DM, ln_b + i * DM);

        // 2) in_proj: [N,256] x [1024,256]^T -> [N,1024] bf16  (mma, 4-stage)
        gemm_bf_big<0><<<dim3((2 * DI) / 128, NTOK / 128), 256, GEMMB_SMEM>>>(
            p_lnbf, DM, wl, p_xzbf, 2 * DI, DM, nullptr, nullptr);

        // 3) causal conv4 + bias + SiLU (bf16 in/out, 4 timesteps/thread)
        conv_silu_kernel<<<(NTOK * DI / 4) / 256, 256>>>(cw + i * DI * 4, cb + i * DI);

        // 4) x_proj: [N,512] x [48,512]^T -> [N,48]  (bf16 mma, N padded to 64)
        gemm_bf_narrow<48><<<dim3(1, NTOK / 128), 256, GEMMN_SMEM>>>(
            p_ubf, DI, wl + W_XP_OFF, p_xdbl, 48, DI);

        // 5) selective scan with fused dt_proj + D skip + z gating (-> bf16 y)
        scan_kernel<<<(BATCH * DI) / 16, 256>>>(
            alog + (size_t)i * DI * DS, dp + i * DI,
            dtw + (size_t)i * DI * 16, dtb + i * DI);

        // 6) out_proj fused with residual + layer_scale: out = xin + ls * (y @ ow^T)
        gemm_bf_big<1><<<dim3(DM / 128, NTOK / 128), 256, GEMMB_SMEM>>>(
            p_ybf, DI, wl + W_OW_OFF, out, DM, DI, xin, ls + i * DM);
    }
}

// round 16
// speedup vs baseline: 1.0468x; 1.0114x over previous
#include <cuda_runtime.h>
#include <cuda_bf16.h>
#include <stdint.h>
#include <math.h>

#define NTOK  16384
#define BATCH 8
#define SEQ   2048
#define DM    256
#define DI    512
#define DS    16

// weight scratch layout per layer: [inw 1024*256 | xpw 48*512 | ow 256*512]
#define W_INP_SZ (1024 * 256)
#define W_XP_OFF W_INP_SZ
#define W_XP_SZ  (48 * 512)
#define W_OW_OFF (W_XP_OFF + W_XP_SZ)
#define W_OW_SZ  (256 * 512)
#define W_LAYER  (W_OW_OFF + W_OW_SZ)

// ---------------- scratch (allocation-free: __device__ globals) ----------------
__device__ __nv_bfloat16 g_lnbf[NTOK * DM];     // layernorm output (bf16)
__device__ __nv_bfloat16 g_xzbf[NTOK * 2 * DI]; // in_proj output (u | z) bf16
__device__ __nv_bfloat16 g_ubf[NTOK * DI];      // conv+silu output (bf16)
__device__ float         g_xdbl[NTOK * 48];     // x_proj output (dt_r | B | C)
__device__ __nv_bfloat16 g_ybf[NTOK * DI];      // scan output, gated (bf16)
__device__ __nv_bfloat16 g_wbf[2 * W_LAYER];    // bf16 weights

__device__ __forceinline__ float sigmoidf_(float v) { return 1.f / (1.f + __expf(-v)); }

__device__ __forceinline__ unsigned smem_u32(const void* p) {
    return (unsigned)__cvta_generic_to_shared(p);
}
__device__ __forceinline__ void cp16(unsigned dst, const void* src) {
    asm volatile("cp.async.cg.shared.global [%0], [%1], 16;" :: "r"(dst), "l"(src));
}

// ---------------- one-shot weight conversion, split into two launches -----------
// (split so the ncu capture slot lands on in_proj: conv_a, conv_b, ln, in_proj)
__global__ void convert_weights_a(const float* __restrict__ inw) {
    int idx = blockIdx.x * 256 + threadIdx.x;
    if (idx >= 2 * W_INP_SZ) return;
    int layer = idx / W_INP_SZ, r = idx % W_INP_SZ;
    g_wbf[(size_t)layer * W_LAYER + r] =
        __float2bfloat16(inw[(size_t)layer * W_INP_SZ + r]);
}
__global__ void convert_weights_b(const float* __restrict__ xpw,
                                  const float* __restrict__ ow) {
    int idx = blockIdx.x * 256 + threadIdx.x;
    int per_layer = W_XP_SZ + W_OW_SZ;
    if (idx >= 2 * per_layer) return;
    int layer = idx / per_layer, r = idx % per_layer;
    float v;
    size_t off;
    if (r < W_XP_SZ) { v = xpw[(size_t)layer * W_XP_SZ + r]; off = W_XP_OFF + r; }
    else             { v = ow[(size_t)layer * W_OW_SZ + (r - W_XP_SZ)]; off = W_OW_OFF + (r - W_XP_SZ); }
    g_wbf[(size_t)layer * W_LAYER + off] = __float2bfloat16(v);
}

// ---------------- layernorm: one warp per token, writes bf16 --------------------
__global__ void ln_kernel(const float* __restrict__ x,
                          const float* __restrict__ g,
                          const float* __restrict__ b) {
    int warp = threadIdx.x >> 5, lane = threadIdx.x & 31;
    int tok = blockIdx.x * 8 + warp;
    const float* row = x + (size_t)tok * DM;
    float v[8];
    float s = 0.f, s2 = 0.f;
#pragma unroll
    for (int i = 0; i < 8; i++) {
        v[i] = row[lane + i * 32];
        s += v[i];
        s2 += v[i] * v[i];
    }
#pragma unroll
    for (int o = 16; o; o >>= 1) {
        s  += __shfl_xor_sync(0xffffffffu, s, o);
        s2 += __shfl_xor_sync(0xffffffffu, s2, o);
    }
    float m   = s * (1.f / DM);
    float var = s2 * (1.f / DM) - m * m;
    float inv = rsqrtf(var + 1e-5f);
    __nv_bfloat16* o = g_lnbf + (size_t)tok * DM;
#pragma unroll
    for (int i = 0; i < 8; i++) {
        int c = lane + i * 32;
        o[c] = __float2bfloat16((v[i] - m) * inv * g[c] + b[c]);
    }
}

// ============ BIG bf16 GEMM: 128x128x32, m16n8k16, 4-stage cp.async =============
// EPI 0: C is bf16 (plain store). EPI 1: C is fp32, res + ls[n]*acc.
#define BB_STR  40
#define BB_ABUF (128 * BB_STR)
#define BB_STAGE (2 * BB_ABUF)
#define GEMMB_SMEM (4 * BB_STAGE * 2)

template <int EPI>
__global__ __launch_bounds__(256)
void gemm_bf_big(const __nv_bfloat16* __restrict__ A, int lda,
                 const __nv_bfloat16* __restrict__ W,
                 void* __restrict__ Cptr,
                 int N, int K,
                 const float* __restrict__ res,
                 const float* __restrict__ ls) {
    extern __shared__ char smem_raw[];
    __nv_bfloat16* dyn = (__nv_bfloat16*)smem_raw;

    const int tid = threadIdx.x;
    const int warp = tid >> 5, lane = tid & 31;
    const int wm = (warp >> 2) * 64;
    const int wn = (warp & 3) * 32;
    const int m0 = blockIdx.y * 128, n0 = blockIdx.x * 128;
    const int lq = lane >> 2, lp = lane & 3;

    auto issue_tile = [&](int st, int k0) {
        __nv_bfloat16* As = dyn + st * BB_STAGE;
        __nv_bfloat16* Ws = As + BB_ABUF;
#pragma unroll
        for (int t = 0; t < 2; t++) {
            int fidx = tid + t * 256;
            int m = fidx >> 2, kc = fidx & 3;
            cp16(smem_u32(&As[m * BB_STR + kc * 8]),
                 &A[(size_t)(m0 + m) * lda + k0 + kc * 8]);
        }
#pragma unroll
        for (int t = 0; t < 2; t++) {
            int fidx = tid + t * 256;
            int n = fidx >> 2, kc = fidx & 3;
            cp16(smem_u32(&Ws[n * BB_STR + kc * 8]),
                 &W[(size_t)(n0 + n) * K + k0 + kc * 8]);
        }
        asm volatile("cp.async.commit_group;");
    };

    float acc[4][4][4];
#pragma unroll
    for (int i = 0; i < 4; i++)
#pragma unroll
        for (int j = 0; j < 4; j++)
#pragma unroll
            for (int q = 0; q < 4; q++) acc[i][j][q] = 0.f;

    const int nit = K / 32;
    issue_tile(0, 0);
    if (nit > 1) issue_tile(1, 32);
    if (nit > 2) issue_tile(2, 64);

    for (int it = 0; it < nit; it++) {
        if (it + 1 < nit) {
            if (it + 2 < nit) asm volatile("cp.async.wait_group 2;");
            else              asm volatile("cp.async.wait_group 1;");
        } else {
            asm volatile("cp.async.wait_group 0;");
        }
        __syncthreads();
        if (it + 3 < nit) issue_tile((it + 3) & 3, (it + 3) * 32);

        const __nv_bfloat16* ab = dyn + (it & 3) * BB_STAGE;
        const __nv_bfloat16* wb = ab + BB_ABUF;
#pragma unroll
        for (int kk = 0; kk < 2; kk++) {
            const int kb = kk * 16;
            unsigned int a[4][4], b[4][2];
#pragma unroll
            for (int mf = 0; mf < 4; mf++) {
                int r = wm + mf * 16 + lq;
                a[mf][0] = *(const unsigned*)&ab[r * BB_STR + kb + lp * 2];
                a[mf][1] = *(const unsigned*)&ab[(r + 8) * BB_STR + kb + lp * 2];
                a[mf][2] = *(const unsigned*)&ab[r * BB_STR + kb + 8 + lp * 2];
                a[mf][3] = *(const unsigned*)&ab[(r + 8) * BB_STR + kb + 8 + lp * 2];
            }
#pragma unroll
            for (int nf = 0; nf < 4; nf++) {
                int n = wn + nf * 8 + lq;
                b[nf][0] = *(const unsigned*)&wb[n * BB_STR + kb + lp * 2];
                b[nf][1] = *(const unsigned*)&wb[n * BB_STR + kb + 8 + lp * 2];
            }
#pragma unroll
            for (int mf = 0; mf < 4; mf++)
#pragma unroll
                for (int nf = 0; nf < 4; nf++) {
                    asm volatile(
                        "mma.sync.aligned.m16n8k16.row.col.f32.bf16.bf16.f32 "
                        "{%0,%1,%2,%3},{%4,%5,%6,%7},{%8,%9},{%0,%1,%2,%3};"
                        : "+f"(acc[mf][nf][0]), "+f"(acc[mf][nf][1]),
                          "+f"(acc[mf][nf][2]), "+f"(acc[mf][nf][3])
                        : "r"(a[mf][0]), "r"(a[mf][1]), "r"(a[mf][2]), "r"(a[mf][3]),
                          "r"(b[nf][0]), "r"(b[nf][1]));
                }
        }
        __syncthreads();
    }

#pragma unroll
    for (int mf = 0; mf < 4; mf++) {
#pragma unroll
        for (int nf = 0; nf < 4; nf++) {
            int r0 = m0 + wm + mf * 16 + lq;
            int c0 = n0 + wn + nf * 8 + lp * 2;
            if (EPI == 0) {
                __nv_bfloat16* C = (__nv_bfloat16*)Cptr;
                *(__nv_bfloat162*)&C[(size_t)r0 * N + c0] =
                    __floats2bfloat162_rn(acc[mf][nf][0], acc[mf][nf][1]);
                *(__nv_bfloat162*)&C[(size_t)(r0 + 8) * N + c0] =
                    __floats2bfloat162_rn(acc[mf][nf][2], acc[mf][nf][3]);
            } else {
                float* C = (float*)Cptr;
                float2 v0 = make_float2(acc[mf][nf][0], acc[mf][nf][1]);
                float2 v1 = make_float2(acc[mf][nf][2], acc[mf][nf][3]);
                float2 r0v = *(const float2*)&res[(size_t)r0 * N + c0];
                float2 r1v = *(const float2*)&res[(size_t)(r0 + 8) * N + c0];
                float l0 = ls[c0], l1 = ls[c0 + 1];
                v0.x = r0v.x + l0 * v0.x; v0.y = r0v.y + l1 * v0.y;
                v1.x = r1v.x + l0 * v1.x; v1.y = r1v.y + l1 * v1.y;
                *(float2*)&C[(size_t)r0 * N + c0] = v0;
                *(float2*)&C[(size_t)(r0 + 8) * N + c0] = v1;
            }
        }
    }
}

// ============ narrow bf16 GEMM (x_proj): 128x64x32, double-buffered =============
#define NB_ABUF (128 * BB_STR)
#define NB_WBUF (64 * BB_STR)
#define GEMMN_SMEM ((2 * NB_ABUF + 2 * NB_WBUF) * 2)

template <int NVALID>
__global__ __launch_bounds__(256)
void gemm_bf_narrow(const __nv_bfloat16* __restrict__ A, int lda,
                    const __nv_bfloat16* __restrict__ W,
                    float* __restrict__ C,
                    int N, int K) {
    extern __shared__ char smem_raw[];
    __nv_bfloat16* As = (__nv_bfloat16*)smem_raw;
    __nv_bfloat16* Ws = As + 2 * NB_ABUF;

    const int tid = threadIdx.x;
    const int warp = tid >> 5, lane = tid & 31;
    const int wm = (warp >> 1) * 32;
    const int wn = (warp & 1) * 32;
    const int m0 = blockIdx.y * 128, n0 = blockIdx.x * 64;
    const int lq = lane >> 2, lp = lane & 3;

    if (NVALID < 64) {
        for (int i = tid; i < 2 * NB_WBUF; i += 256) {
            int row = (i % NB_WBUF) / BB_STR;
            if (row >= NVALID) Ws[i] = __float2bfloat16(0.f);
        }
    }

    auto issue_tile = [&](int buf, int k0) {
#pragma unroll
        for (int t = 0; t < 2; t++) {
            int fidx = tid + t * 256;
            int m = fidx >> 2, kc = fidx & 3;
            cp16(smem_u32(&As[buf * NB_ABUF + m * BB_STR + kc * 8]),
                 &A[(size_t)(m0 + m) * lda + k0 + kc * 8]);
        }
        {
            int n = tid >> 2, kc = tid & 3;
            if (NVALID == 64 || n < NVALID)
                cp16(smem_u32(&Ws[buf * NB_WBUF + n * BB_STR + kc * 8]),
                     &W[(size_t)(n0 + n) * K + k0 + kc * 8]);
        }
        asm volatile("cp.async.commit_group;");
    };

    float acc[2][4][4];
#pragma unroll
    for (int i = 0; i < 2; i++)
#pragma unroll
        for (int j = 0; j < 4; j++)
#pragma unroll
            for (int q = 0; q < 4; q++) acc[i][j][q] = 0.f;

    const int nit = K / 32;
    issue_tile(0, 0);

    for (int it = 0; it < nit; it++) {
        int buf = it & 1;
        if (it + 1 < nit) {
            issue_tile(buf ^ 1, (it + 1) * 32);
            asm volatile("cp.async.wait_group 1;");
        } else {
            asm volatile("cp.async.wait_group 0;");
        }
        __syncthreads();

        const __nv_bfloat16* ab = As + buf * NB_ABUF;
        const __nv_bfloat16* wb = Ws + buf * NB_WBUF;
#pragma unroll
        for (int kk = 0; kk < 2; kk++) {
            const int kb = kk * 16;
            unsigned int a[2][4], b[4][2];
#pragma unroll
            for (int mf = 0; mf < 2; mf++) {
                int r = wm + mf * 16 + lq;
                a[mf][0] = *(const unsigned*)&ab[r * BB_STR + kb + lp * 2];
                a[mf][1] = *(const unsigned*)&ab[(r + 8) * BB_STR + kb + lp * 2];
                a[mf][2] = *(const unsigned*)&ab[r * BB_STR + kb + 8 + lp * 2];
                a[mf][3] = *(const unsigned*)&ab[(r + 8) * BB_STR + kb + 8 + lp * 2];
            }
#pragma unroll
            for (int nf = 0; nf < 4; nf++) {
                int n = wn + nf * 8 + lq;
                b[nf][0] = *(const unsigned*)&wb[n * BB_STR + kb + lp * 2];
                b[nf][1] = *(const unsigned*)&wb[n * BB_STR + kb + 8 + lp * 2];
            }
#pragma unroll
            for (int mf = 0; mf < 2; mf++)
#pragma unroll
                for (int nf = 0; nf < 4; nf++) {
                    asm volatile(
                        "mma.sync.aligned.m16n8k16.row.col.f32.bf16.bf16.f32 "
                        "{%0,%1,%2,%3},{%4,%5,%6,%7},{%8,%9},{%0,%1,%2,%3};"
                        : "+f"(acc[mf][nf][0]), "+f"(acc[mf][nf][1]),
                          "+f"(acc[mf][nf][2]), "+f"(acc[mf][nf][3])
                        : "r"(a[mf][0]), "r"(a[mf][1]), "r"(a[mf][2]), "r"(a[mf][3]),
                          "r"(b[nf][0]), "r"(b[nf][1]));
                }
        }
        __syncthreads();
    }

#pragma unroll
    for (int mf = 0; mf < 2; mf++) {
#pragma unroll
        for (int nf = 0; nf < 4; nf++) {
            int r0 = m0 + wm + mf * 16 + lq;
            int c0 = n0 + wn + nf * 8 + lp * 2;
            if (NVALID < 64 && c0 >= NVALID) continue;
            float2 v0 = make_float2(acc[mf][nf][0], acc[mf][nf][1]);
            float2 v1 = make_float2(acc[mf][nf][2], acc[mf][nf][3]);
            *(float2*)&C[(size_t)r0 * N + c0] = v0;
            *(float2*)&C[(size_t)(r0 + 8) * N + c0] = v1;
        }
    }
}

// -------- causal depthwise conv(4) + bias + SiLU: 4 timesteps per thread --------
__global__ void conv_silu_kernel(const float* __restrict__ cw,
                                 const float* __restrict__ cb) {
    int idx = blockIdx.x * 256 + threadIdx.x;    // over NTOK*DI/4
    int d = idx & (DI - 1);
    int g = idx >> 9;                            // 4-token group
    int n0 = g << 2;
    int l0 = n0 & (SEQ - 1);

    float w0 = cw[d * 4 + 0], w1 = cw[d * 4 + 1];
    float w2 = cw[d * 4 + 2], w3 = cw[d * 4 + 3];
    float bias = cb[d];

    float xv[7];
#pragma unroll
    for (int j = 0; j < 7; j++) {
        int ll = l0 - 3 + j;
        xv[j] = (ll >= 0)
            ? __bfloat162float(g_xzbf[(size_t)(n0 - 3 + j) * (2 * DI) + d])
            : 0.f;
    }

#pragma unroll
    for (int t = 0; t < 4; t++) {
        float acc = bias;
        acc = fmaf(w0, xv[t + 0], acc);
        acc = fmaf(w1, xv[t + 1], acc);
        acc = fmaf(w2, xv[t + 2], acc);
        acc = fmaf(w3, xv[t + 3], acc);
        float su = acc * sigmoidf_(acc);
        g_ubf[(size_t)(n0 + t) * DI + d] = __float2bfloat16(su);
    }
}

// ---------------- selective scan: shuffle-free, TCH=32 chunks (R13) -------------
// dA uses exp2f with log2(e) pre-folded into As (saves an FMUL per step).
#define TCH 32
__global__ __launch_bounds__(256)
void scan_kernel(const float* __restrict__ A_log,
                 const float* __restrict__ Dp,
                 const float* __restrict__ dtw,   // [DI,16]
                 const float* __restrict__ dtb) { // [DI]
    __shared__ float sx[TCH * 48];
    __shared__ float su_[TCH][17], sz_[TCH][17], sdt_[TCH][17];
    __shared__ float sdtw[16][17];
    __shared__ float sp[8][TCH][33];

    int tid = threadIdx.x;
    int ch = tid >> 4;
    int s = tid & 15;
    int w = tid >> 5;
    int lane = tid & 31;
    int b = blockIdx.x >> 5;
    int d0 = (blockIdx.x & 31) << 4;
    int d = d0 + ch;

    int lt = tid >> 4, lj = tid & 15;

    sdtw[s][ch] = dtw[(d0 + ch) * 16 + s];
    float dtb_j = dtb[d0 + lj];

    // fold log2(e) so dA = exp2(r * As2): one FFMA feeds MUFU.EX2 directly
    float As2 = -__expf(A_log[d * DS + s]) * 1.44269504f;
    float h = 0.f;
    size_t base = (size_t)b * SEQ;

    float Dv0 = Dp[d0 + 2 * w], Dv1 = Dp[d0 + 2 * w + 1];

    float p_x[6], p_u0, p_u1, p_z0, p_z1;
    {
        const float* xrow = g_xdbl + base * 48;
#pragma unroll
        for (int i = 0; i < 6; i++) p_x[i] = xrow[tid + i * 256];
        p_u0 = __bfloat162float(g_ubf[(base + lt) * DI + d0 + lj]);
        p_u1 = __bfloat162float(g_ubf[(base + lt + 16) * DI + d0 + lj]);
        p_z0 = __bfloat162float(g_xzbf[(base + lt) * (2 * DI) + DI + d0 + lj]);
        p_z1 = __bfloat162float(g_xzbf[(base + lt + 16) * (2 * DI) + DI + d0 + lj]);
    }

    for (int l0 = 0; l0 < SEQ; l0 += TCH) {
        __syncthreads();
#pragma unroll
        for (int i = 0; i < 6; i++) sx[tid + i * 256] = p_x[i];
        su_[lt][lj] = p_u0; su_[lt + 16][lj] = p_u1;
        sz_[lt][lj] = p_z0; sz_[lt + 16][lj] = p_z1;
        __syncthreads();

        {
            float v0 = dtb_j, v1 = dtb_j;
#pragma unroll
            for (int r = 0; r < 16; r++) {
                float wv = sdtw[r][lj];
                v0 = fmaf(sx[lt * 48 + r], wv, v0);
                v1 = fmaf(sx[(lt + 16) * 48 + r], wv, v1);
            }
            sdt_[lt][lj]      = (v0 > 20.f) ? v0 : log1pf(__expf(v0));
            sdt_[lt + 16][lj] = (v1 > 20.f) ? v1 : log1pf(__expf(v1));
        }

        if (l0 + TCH < SEQ) {
            const float* xrow = g_xdbl + (base + l0 + TCH) * 48;
#pragma unroll
            for (int i = 0; i < 6; i++) p_x[i] = xrow[tid + i * 256];
            size_t n = base + l0 + TCH + lt;
            p_u0 = __bfloat162float(g_ubf[n * DI + d0 + lj]);
            p_u1 = __bfloat162float(g_ubf[(n + 16) * DI + d0 + lj]);
            p_z0 = __bfloat162float(g_xzbf[n * (2 * DI) + DI + d0 + lj]);
            p_z1 = __bfloat162float(g_xzbf[(n + 16) * (2 * DI) + DI + d0 + lj]);
        }
        __syncthreads();

        // ---- phase 1: recurrence, h*C straight to transpose buffer ----
#pragma unroll
        for (int t = 0; t < TCH; t++) {
            float r  = sdt_[t][ch];
            float uu = su_[t][ch];
            float dA = exp2f(r * As2);
            h = fmaf(dA, h, (r * uu) * sx[t * 48 + 16 + s]);
            sp[w][t][lane] = h * sx[t * 48 + 32 + s];
        }
        __syncwarp();

        // ---- phase 2: lane t sums 16 states for the warp's 2 channels ----
        float a0 = 0.f, a1 = 0.f;
#pragma unroll
        for (int k = 0; k < 16; k++) {
            a0 += sp[w][lane][k];
            a1 += sp[w][lane][16 + k];
        }
        float uu0 = su_[lane][2 * w],     zz0 = sz_[lane][2 * w];
        float uu1 = su_[lane][2 * w + 1], zz1 = sz_[lane][2 * w + 1];
        float y0 = (a0 + uu0 * Dv0) * (zz0 * sigmoidf_(zz0));
        float y1 = (a1 + uu1 * Dv1) * (zz1 * sigmoidf_(zz1));
        *(__nv_bfloat162*)&g_ybf[(base + l0 + lane) * DI + d0 + 2 * w] =
            __floats2bfloat162_rn(y0, y1);
    }
}

// ---------------- host orchestration --------------------------------------------
extern "C" void kernel_launch(void* const* d_in, const int* in_sizes, int n_in,
                              void* d_out, int out_size) {
    const float* x    = (const float*)d_in[0];
    const float* ln_g = (const float*)d_in[1];
    const float* ln_b = (const float*)d_in[2];
    const float* inw  = (const float*)d_in[3];   // [2,1024,256]
    const float* cw   = (const float*)d_in[4];   // [2,512,4]
    const float* cb   = (const float*)d_in[5];   // [2,512]
    const float* xpw  = (const float*)d_in[6];   // [2,48,512]
    const float* dtw  = (const float*)d_in[7];   // [2,512,16]
    const float* dtb  = (const float*)d_in[8];   // [2,512]
    const float* alog = (const float*)d_in[9];   // [2,512,16]
    const float* dp   = (const float*)d_in[10];  // [2,512]
    const float* ow   = (const float*)d_in[11];  // [2,256,512]
    const float* ls   = (const float*)d_in[12];  // [2,256]
    float* out = (float*)d_out;

    cudaFuncSetAttribute(gemm_bf_big<0>, cudaFuncAttributeMaxDynamicSharedMemorySize, GEMMB_SMEM);
    cudaFuncSetAttribute(gemm_bf_big<1>, cudaFuncAttributeMaxDynamicSharedMemorySize, GEMMB_SMEM);
    cudaFuncSetAttribute(gemm_bf_narrow<48>, cudaFuncAttributeMaxDynamicSharedMemorySize, GEMMN_SMEM);

    __nv_bfloat16 *p_lnbf, *p_xzbf, *p_ubf, *p_ybf, *p_wbf;
    float *p_xdbl;
    cudaGetSymbolAddress((void**)&p_lnbf, g_lnbf);
    cudaGetSymbolAddress((void**)&p_xzbf, g_xzbf);
    cudaGetSymbolAddress((void**)&p_ubf,  g_ubf);
    cudaGetSymbolAddress((void**)&p_xdbl, g_xdbl);
    cudaGetSymbolAddress((void**)&p_ybf,  g_ybf);
    cudaGetSymbolAddress((void**)&p_wbf,  g_wbf);

    // 0) weight conversion, split into two launches (capture steering)
    convert_weights_a<<<(2 * W_INP_SZ + 255) / 256, 256>>>(inw);
    convert_weights_b<<<(2 * (W_XP_SZ + W_OW_SZ) + 255) / 256, 256>>>(xpw, ow);

    for (int i = 0; i < 2; i++) {
        const float* xin = (i == 0) ? x : out;
        const __nv_bfloat16* wl = p_wbf + (size_t)i * W_LAYER;

        // 1) layernorm (-> bf16)
        ln_kernel<<<NTOK / 8, 256>>>(xin, ln_g + i * DM, ln_b + i * DM);

        // 2) in_proj: [N,256] x [1024,256]^T -> [N,1024] bf16  (mma, 4-stage)
        gemm_bf_big<0><<<dim3((2 * DI) / 128, NTOK / 128), 256, GEMMB_SMEM>>>(
            p_lnbf, DM, wl, p_xzbf, 2 * DI, DM, nullptr, nullptr);

        // 3) causal conv4 + bias + SiLU (bf16 in/out, 4 timesteps/thread)
        conv_silu_kernel<<<(NTOK * DI / 4) / 256, 256>>>(cw + i * DI * 4, cb + i * DI);

        // 4) x_proj: [N,512] x [48,512]^T -> [N,48]  (bf16 mma, N padded to 64)
        gemm_bf_narrow<48><<<dim3(1, NTOK / 128), 256, GEMMN_SMEM>>>(
            p_ubf, DI, wl + W_XP_OFF, p_xdbl, 48, DI);

        // 5) selective scan with fused dt_proj + D skip + z gating (-> bf16 y)
        scan_kernel<<<(BATCH * DI) / 16, 256>>>(
            alog + (size_t)i * DI * DS, dp + i * DI,
            dtw + (size_t)i * DI * 16, dtb + i * DI);

        // 6) out_proj fused with residual + layer_scale: out = xin + ls * (y @ ow^T)
        gemm_bf_big<1><<<dim3(DM / 128, NTOK / 128), 256, GEMMB_SMEM>>>(
            p_ybf, DI, wl + W_OW_OFF, out, DM, DI, xin, ls + i * DM);
    }
}